// round 3
// baseline (speedup 1.0000x reference)
#include <cuda_runtime.h>
#include <cstdint>

// Problem constants
#define B_TOT  2048
#define S_LEN  256
#define DIN    3
#define HID    128
#define D_OUT  6
#define DT_F   0.1f

// Tiling: 14 batch rows per CTA (2 independent groups x 7 rows), 147 CTAs.
// 512 threads: tp = tid&63 (neuron PAIR), kq = (tid>>6)&3 (quarter-K),
// g = tid>>8 (row group). Warps uniform in (kq,g) -> h loads broadcast.
// The two row-groups share nothing during the scan -> named barriers per group.
#define ROWS   14
#define RPG    7
#define NCTA   ((B_TOT + ROWS - 1) / ROWS)   // 147
#define NTHR   512

typedef unsigned long long u64;

// ---- packed f32x2 FMA (SASS FFMA2; 2 MACs/lane/instr on sm_103a) ----
__device__ __forceinline__ u64 fma2(u64 a, u64 b, u64 c) {
    u64 d;
    asm("fma.rn.f32x2 %0, %1, %2, %3;" : "=l"(d) : "l"(a), "l"(b), "l"(c));
    return d;
}
__device__ __forceinline__ u64 pk(float lo, float hi) {
    u64 v;
    asm("mov.b64 %0, {%1, %2};" : "=l"(v) : "f"(lo), "f"(hi));
    return v;
}
__device__ __forceinline__ void upk(u64 v, float& lo, float& hi) {
    asm("mov.b64 {%0, %1}, %2;" : "=f"(lo), "=f"(hi) : "l"(v));
}

// Accurate-enough tanh: ex2.approx + fast divide; abs err ~1e-6.
__device__ __forceinline__ float fast_tanh(float x) {
    float ax = fminf(fabsf(x), 15.0f);
    float e  = __expf(2.0f * ax);
    float t  = 1.0f - __fdividef(2.0f, e + 1.0f);
    return copysignf(t, x);
}

// softplus(x) = max(x,0) + log1p(exp(-|x|))  (stable, accurate)
__device__ __forceinline__ float softplus_acc(float x) {
    return fmaxf(x, 0.0f) + log1pf(__expf(-fabsf(x)));
}

extern __shared__ float smem_dyn[];

__global__ void __launch_bounds__(NTHR, 1)
cfc_kernel(const float* __restrict__ x,        // [B, S, 3]
           const float* __restrict__ W_xh,     // [128, 3]
           const float* __restrict__ W_hh,     // [128, 128]
           const float* __restrict__ b_hh,     // [128]
           const float* __restrict__ log_tau,  // [128]
           const float* __restrict__ fc_W,     // [6, 128]
           const float* __restrict__ fc_b,     // [6]
           float* __restrict__ out)            // [B, 6]
{
    // Shared layout: x tile | double-buffered h | k-split partial buffer
    float* xsh  = smem_dyn;                       // ROWS*S_LEN*DIN = 10752 floats
    float* hbuf = xsh + ROWS * S_LEN * DIN;       // 2*ROWS*HID    =  3584 floats
    float* part = hbuf + 2 * ROWS * HID;          // 4(kq)*2(g)*RPG*HID = 7168 floats

    const int tid = threadIdx.x;
    const int tp  = tid & 63;            // neuron pair index: owns t0=2tp, t1=2tp+1
    const int kq  = (tid >> 6) & 3;      // quarter-K: j in [kq*32, kq*32+32)
    const int g   = tid >> 8;            // row group (0 or 1)
    const int t0  = 2 * tp;
    const int t1  = 2 * tp + 1;
    const int cb  = blockIdx.x * ROWS;   // global batch-row base

    // ---- W_hh rows t0,t1 (this thread's j-quarter) -> registers as f32x2 pairs ----
    u64 W0[16], W1[16];                  // 32 u64 = 64 x 32-bit regs
    {
        const ulonglong2* w0 = reinterpret_cast<const ulonglong2*>(W_hh + t0 * HID + kq * 32);
        const ulonglong2* w1 = reinterpret_cast<const ulonglong2*>(W_hh + t1 * HID + kq * 32);
        #pragma unroll
        for (int j4 = 0; j4 < 8; j4++) {
            ulonglong2 a = w0[j4];
            W0[2 * j4] = a.x; W0[2 * j4 + 1] = a.y;
            ulonglong2 b = w1[j4];
            W1[2 * j4] = b.x; W1[2 * j4 + 1] = b.y;
        }
    }

    // ---- per-neuron scalars (both neurons) ----
    const float wx00 = W_xh[t0 * 3 + 0], wx01 = W_xh[t0 * 3 + 1], wx02 = W_xh[t0 * 3 + 2];
    const float wx10 = W_xh[t1 * 3 + 0], wx11 = W_xh[t1 * 3 + 1], wx12 = W_xh[t1 * 3 + 2];
    const float bb0 = b_hh[t0], bb1 = b_hh[t1];
    const float aa0 = DT_F / (softplus_acc(log_tau[t0]) + 0.001f);
    const float aa1 = DT_F / (softplus_acc(log_tau[t1]) + 0.001f);

    // ---- stage x tile into SMEM ----
    {
        const int n = ROWS * S_LEN * DIN;
        const float* src = x + (size_t)cb * (S_LEN * DIN);
        int lim = (B_TOT - cb) * (S_LEN * DIN);
        if (lim > n) lim = n;
        for (int i = tid; i < n; i += NTHR)
            xsh[i] = (i < lim) ? src[i] : 0.0f;
    }
    for (int i = tid; i < 2 * ROWS * HID; i += NTHR) hbuf[i] = 0.0f;
    __syncthreads();

    const int rb = g * RPG;                 // local row base for this group
    float* h0 = hbuf;
    float* h1 = hbuf + ROWS * HID;

    // Finish-phase row assignment across kq: 2,2,2,1
    const int r_lo = 2 * kq;
    const int r_hi = (2 * kq + 2 < RPG) ? (2 * kq + 2) : RPG;

    // partial buffer slot for this (kq, g)
    float* my_part = part + ((kq * 2 + g) * RPG) * HID;

    // ================= sequential scan over S =================
    for (int s = 0; s < S_LEN; s++) {
        const float* hc = (s & 1) ? h1 : h0;   // read buffer
        float*       hn = (s & 1) ? h0 : h1;   // write buffer

        // matvec partials over this thread's j-quarter, 2 neurons x RPG rows
        u64 acc0[RPG], acc1[RPG];
        #pragma unroll
        for (int r = 0; r < RPG; r++) { acc0[r] = 0ull; acc1[r] = 0ull; }

        const float* hbase = hc + rb * HID + kq * 32;
        #pragma unroll
        for (int j4 = 0; j4 < 8; j4++) {
            #pragma unroll
            for (int r = 0; r < RPG; r++) {
                // warp-uniform broadcast LDS.128: 4 h floats feed 4 FFMA2 (8 MACs)
                ulonglong2 hv = *reinterpret_cast<const ulonglong2*>(
                    hbase + r * HID + j4 * 4);
                acc0[r] = fma2(W0[2 * j4],     hv.x, acc0[r]);
                acc0[r] = fma2(W0[2 * j4 + 1], hv.y, acc0[r]);
                acc1[r] = fma2(W1[2 * j4],     hv.x, acc1[r]);
                acc1[r] = fma2(W1[2 * j4 + 1], hv.y, acc1[r]);
            }
        }

        // publish partials: u64 per row = (z_t0, z_t1) for this j-quarter
        #pragma unroll
        for (int r = 0; r < RPG; r++) {
            float a, b, c, d;
            upk(acc0[r], a, b);
            upk(acc1[r], c, d);
            *reinterpret_cast<u64*>(my_part + r * HID + t0) = pk(a + b, c + d);
        }
        // group-scoped barrier (the other row-group is independent)
        asm volatile("bar.sync %0, 256;" :: "r"(g + 1) : "memory");

        // finish assigned rows: reduce the other 3 quarters, + x-proj + bias,
        // tanh, leaky update
        #pragma unroll
        for (int r = r_lo; r < r_hi; r++) {
            float a, b, c, d;
            upk(acc0[r], a, b);
            upk(acc1[r], c, d);
            float z0 = a + b, z1 = c + d;
            #pragma unroll
            for (int q = 0; q < 4; q++) {
                if (q == kq) continue;
                u64 pv = *reinterpret_cast<const u64*>(
                    part + ((q * 2 + g) * RPG + r) * HID + t0);
                float q0, q1;
                upk(pv, q0, q1);
                z0 += q0; z1 += q1;
            }
            const float* xr = xsh + (rb + r) * (S_LEN * DIN) + s * 3;
            float x0 = xr[0], x1 = xr[1], x2 = xr[2];
            z0 += fmaf(wx00, x0, fmaf(wx01, x1, fmaf(wx02, x2, bb0)));
            z1 += fmaf(wx10, x0, fmaf(wx11, x1, fmaf(wx12, x2, bb1)));
            float f0 = fast_tanh(z0);
            float f1 = fast_tanh(z1);
            u64 hov = *reinterpret_cast<const u64*>(hc + (rb + r) * HID + t0);
            float ho0, ho1;
            upk(hov, ho0, ho1);
            float hn0 = fmaf(aa0, f0 - ho0, ho0);
            float hn1 = fmaf(aa1, f1 - ho1, ho1);
            *reinterpret_cast<u64*>(hn + (rb + r) * HID + t0) = pk(hn0, hn1);
        }
        // second group barrier: next matvec reads hn; partials get overwritten
        asm volatile("bar.sync %0, 256;" :: "r"(g + 1) : "memory");
    }

    __syncthreads();   // join both groups before the head

    // ================= output head: softplus(h_T @ fc_W^T + fc_b) =================
    const float* hf = h0;   // S_LEN even -> final state in buffer 0
    if (tid < ROWS * D_OUT) {
        const int r = tid / D_OUT;
        const int o = tid % D_OUT;
        const int grow = cb + r;
        if (grow < B_TOT) {
            const float4* w4 = reinterpret_cast<const float4*>(fc_W + o * HID);
            const float4* h4 = reinterpret_cast<const float4*>(hf + r * HID);
            float z = fc_b[o];
            #pragma unroll
            for (int j = 0; j < HID / 4; j++) {
                float4 w = w4[j];
                float4 h = h4[j];
                z = fmaf(w.x, h.x, fmaf(w.y, h.y, fmaf(w.z, h.z, fmaf(w.w, h.w, z))));
            }
            out[grow * D_OUT + o] = softplus_acc(z);
        }
    }
}

extern "C" void kernel_launch(void* const* d_in, const int* in_sizes, int n_in,
                              void* d_out, int out_size) {
    const float* x       = (const float*)d_in[0];
    const float* W_xh    = (const float*)d_in[1];
    const float* W_hh    = (const float*)d_in[2];
    const float* b_hh    = (const float*)d_in[3];
    const float* log_tau = (const float*)d_in[4];
    const float* fc_W    = (const float*)d_in[5];
    const float* fc_b    = (const float*)d_in[6];
    float* out = (float*)d_out;

    const size_t shmem = (size_t)(ROWS * S_LEN * DIN + 2 * ROWS * HID
                                  + 4 * 2 * RPG * HID) * sizeof(float);  // 86016 B
    cudaFuncSetAttribute(cfc_kernel, cudaFuncAttributeMaxDynamicSharedMemorySize, (int)shmem);

    cfc_kernel<<<NCTA, NTHR, shmem>>>(x, W_xh, W_hh, b_hh, log_tau, fc_W, fc_b, out);
}

// round 4
// speedup vs baseline: 1.1123x; 1.1123x over previous
#include <cuda_runtime.h>
#include <cstdint>

// Problem constants
#define B_TOT  2048
#define S_LEN  256
#define DIN    3
#define HID    128
#define D_OUT  6
#define DT_F   0.1f

// 14 batch rows per CTA, 147 CTAs (one wave).
// 512 threads: tp = tid&31 (neuron QUAD: n0=4tp..4tp+3), ks = (tid>>5)&7
// (K-slice: 16 cols), rh = tid>>8 (row half: 7 rows). Warps uniform in
// (ks, rh) -> all h loads are warp-uniform broadcasts.
// h is stored SPLATTED in smem: hsp[row][2j] = hsp[row][2j+1] = h[j], so one
// LDS.128 yields (hj,hj,hj+1,hj+1) which feeds neuron-packed f32x2 FMAs
// directly (no splat instructions, no horizontal sums).
#define ROWS   14
#define RPG    7
#define NCTA   ((B_TOT + ROWS - 1) / ROWS)   // 147
#define NTHR   512
#define SPC    (2 * HID)                     // splat row pitch: 256 floats

#define XSZ    (ROWS * S_LEN * DIN)          // 10752 floats
#define HSPSZ  (ROWS * SPC)                  // 3584 floats per buffer
#define PARTSZ (8 * ROWS * HID)              // 14336 floats

typedef unsigned long long u64;

// ---- packed f32x2 FMA (SASS FFMA2) ----
__device__ __forceinline__ u64 fma2(u64 a, u64 b, u64 c) {
    u64 d;
    asm("fma.rn.f32x2 %0, %1, %2, %3;" : "=l"(d) : "l"(a), "l"(b), "l"(c));
    return d;
}
__device__ __forceinline__ u64 pk(float lo, float hi) {
    u64 v;
    asm("mov.b64 %0, {%1, %2};" : "=l"(v) : "f"(lo), "f"(hi));
    return v;
}
__device__ __forceinline__ void upk(u64 v, float& lo, float& hi) {
    asm("mov.b64 {%0, %1}, %2;" : "=f"(lo), "=f"(hi) : "l"(v));
}

// Accurate-enough tanh: ex2.approx + fast divide; abs err ~1e-6.
__device__ __forceinline__ float fast_tanh(float x) {
    float ax = fminf(fabsf(x), 15.0f);
    float e  = __expf(2.0f * ax);
    float t  = 1.0f - __fdividef(2.0f, e + 1.0f);
    return copysignf(t, x);
}

// softplus(x) = max(x,0) + log1p(exp(-|x|))  (stable, accurate)
__device__ __forceinline__ float softplus_acc(float x) {
    return fmaxf(x, 0.0f) + log1pf(__expf(-fabsf(x)));
}

extern __shared__ float smem_dyn[];

__global__ void __launch_bounds__(NTHR, 1)
cfc_kernel(const float* __restrict__ x,        // [B, S, 3]
           const float* __restrict__ W_xh,     // [128, 3]
           const float* __restrict__ W_hh,     // [128, 128]
           const float* __restrict__ b_hh,     // [128]
           const float* __restrict__ log_tau,  // [128]
           const float* __restrict__ fc_W,     // [6, 128]
           const float* __restrict__ fc_b,     // [6]
           float* __restrict__ out)            // [B, 6]
{
    float* xsh  = smem_dyn;            // x tile
    float* hsp0 = xsh + XSZ;           // splatted h, buffer 0
    float* hsp1 = hsp0 + HSPSZ;        // splatted h, buffer 1
    float* part = hsp1 + HSPSZ;        // k-split partials [ks][row][neuron]

    const int tid = threadIdx.x;
    const int tp  = tid & 31;            // neuron quad: n0 = 4tp .. 4tp+3
    const int ks  = (tid >> 5) & 7;      // K-slice: cols [ks*16, ks*16+16)
    const int rh  = tid >> 8;            // row half: rows [rh*7, rh*7+7)
    const int n0  = 4 * tp;
    const int colb = ks * 16;
    const int rowb = rh * RPG;
    const int cb  = blockIdx.x * ROWS;   // global batch-row base

    // ---- W_hh: neuron-interleaved pairs. W01[c]=(W[n0][c],W[n1][c]) etc. ----
    u64 W01[16], W23[16];
    {
        const float* w0 = W_hh + (n0 + 0) * HID + colb;
        const float* w1 = W_hh + (n0 + 1) * HID + colb;
        const float* w2 = W_hh + (n0 + 2) * HID + colb;
        const float* w3 = W_hh + (n0 + 3) * HID + colb;
        #pragma unroll
        for (int c = 0; c < 16; c++) {
            W01[c] = pk(w0[c], w1[c]);
            W23[c] = pk(w2[c], w3[c]);
        }
    }

    // ---- per-neuron leak coefficients (finish-phase params come from L1) ----
    float aa[4];
    #pragma unroll
    for (int i = 0; i < 4; i++)
        aa[i] = DT_F / (softplus_acc(log_tau[n0 + i]) + 0.001f);

    // ---- stage x tile; zero splat-h buffers ----
    {
        const int n = XSZ;
        const float* src = x + (size_t)cb * (S_LEN * DIN);
        int lim = (B_TOT - cb) * (S_LEN * DIN);
        if (lim > n) lim = n;
        for (int i = tid; i < n; i += NTHR)
            xsh[i] = (i < lim) ? src[i] : 0.0f;
    }
    for (int i = tid; i < 2 * HSPSZ; i += NTHR) hsp0[i] = 0.0f;
    __syncthreads();

    // ================= sequential scan over S =================
    for (int s = 0; s < S_LEN; s++) {
        const float* hcur = (s & 1) ? hsp1 : hsp0;
        float*       hnxt = (s & 1) ? hsp0 : hsp1;

        // ---- matvec partials: 4 neurons x 7 rows over 16 cols ----
        u64 a01[RPG], a23[RPG];
        #pragma unroll
        for (int r = 0; r < RPG; r++) { a01[r] = 0ull; a23[r] = 0ull; }

        const float* hb = hcur + rowb * SPC + colb * 2;
        #pragma unroll
        for (int c2 = 0; c2 < 8; c2++) {   // 2 cols per iteration
            // rows 0..3
            ulonglong2 hvA[4];
            #pragma unroll
            for (int r = 0; r < 4; r++)
                hvA[r] = *reinterpret_cast<const ulonglong2*>(hb + r * SPC + c2 * 4);
            #pragma unroll
            for (int r = 0; r < 4; r++) a01[r] = fma2(W01[2 * c2],     hvA[r].x, a01[r]);
            #pragma unroll
            for (int r = 0; r < 4; r++) a23[r] = fma2(W23[2 * c2],     hvA[r].x, a23[r]);
            #pragma unroll
            for (int r = 0; r < 4; r++) a01[r] = fma2(W01[2 * c2 + 1], hvA[r].y, a01[r]);
            #pragma unroll
            for (int r = 0; r < 4; r++) a23[r] = fma2(W23[2 * c2 + 1], hvA[r].y, a23[r]);
            // rows 4..6
            ulonglong2 hvB[3];
            #pragma unroll
            for (int r = 0; r < 3; r++)
                hvB[r] = *reinterpret_cast<const ulonglong2*>(hb + (4 + r) * SPC + c2 * 4);
            #pragma unroll
            for (int r = 0; r < 3; r++) a01[4 + r] = fma2(W01[2 * c2],     hvB[r].x, a01[4 + r]);
            #pragma unroll
            for (int r = 0; r < 3; r++) a23[4 + r] = fma2(W23[2 * c2],     hvB[r].x, a23[4 + r]);
            #pragma unroll
            for (int r = 0; r < 3; r++) a01[4 + r] = fma2(W01[2 * c2 + 1], hvB[r].y, a01[4 + r]);
            #pragma unroll
            for (int r = 0; r < 3; r++) a23[4 + r] = fma2(W23[2 * c2 + 1], hvB[r].y, a23[4 + r]);
        }

        // ---- publish partials (neuron-packed; lane-contiguous STS.128) ----
        #pragma unroll
        for (int r = 0; r < RPG; r++) {
            ulonglong2 v;
            v.x = a01[r];
            v.y = a23[r];
            *reinterpret_cast<ulonglong2*>(part + (ks * ROWS + rowb + r) * HID + n0) = v;
        }
        asm volatile("bar.sync %0, 256;" :: "r"(rh + 1) : "memory");

        // ---- finish: ks 0..6 each finish one row of this half ----
        if (ks < RPG) {
            const int row = rowb + ks;
            float z0 = 0.f, z1 = 0.f, z2 = 0.f, z3 = 0.f;
            #pragma unroll
            for (int q = 0; q < 8; q++) {
                ulonglong2 pv = *reinterpret_cast<const ulonglong2*>(
                    part + (q * ROWS + row) * HID + n0);
                float p0, p1, p2, p3;
                upk(pv.x, p0, p1);
                upk(pv.y, p2, p3);
                z0 += p0; z1 += p1; z2 += p2; z3 += p3;
            }
            // x projection params from gmem (L1-resident after step 0)
            const float4* wxa = reinterpret_cast<const float4*>(W_xh);
            float4 wa = wxa[3 * tp + 0];
            float4 wb = wxa[3 * tp + 1];
            float4 wc = wxa[3 * tp + 2];
            float4 b4 = reinterpret_cast<const float4*>(b_hh)[tp];
            const float* xr = xsh + row * (S_LEN * DIN) + s * 3;
            float x0 = xr[0], x1 = xr[1], x2 = xr[2];
            z0 += fmaf(wa.x, x0, fmaf(wa.y, x1, fmaf(wa.z, x2, b4.x)));
            z1 += fmaf(wa.w, x0, fmaf(wb.x, x1, fmaf(wb.y, x2, b4.y)));
            z2 += fmaf(wb.z, x0, fmaf(wb.w, x1, fmaf(wc.x, x2, b4.z)));
            z3 += fmaf(wc.y, x0, fmaf(wc.z, x1, fmaf(wc.w, x2, b4.w)));
            float f0 = fast_tanh(z0), f1 = fast_tanh(z1);
            float f2 = fast_tanh(z2), f3 = fast_tanh(z3);
            // old h from splat buffer
            ulonglong2 hv0 = *reinterpret_cast<const ulonglong2*>(hcur + row * SPC + 8 * tp);
            ulonglong2 hv1 = *reinterpret_cast<const ulonglong2*>(hcur + row * SPC + 8 * tp + 4);
            float h0, h1, h2, h3, junk;
            upk(hv0.x, h0, junk);
            upk(hv0.y, h1, junk);
            upk(hv1.x, h2, junk);
            upk(hv1.y, h3, junk);
            h0 = fmaf(aa[0], f0 - h0, h0);
            h1 = fmaf(aa[1], f1 - h1, h1);
            h2 = fmaf(aa[2], f2 - h2, h2);
            h3 = fmaf(aa[3], f3 - h3, h3);
            ulonglong2 o0, o1;
            o0.x = pk(h0, h0); o0.y = pk(h1, h1);
            o1.x = pk(h2, h2); o1.y = pk(h3, h3);
            *reinterpret_cast<ulonglong2*>(hnxt + row * SPC + 8 * tp)     = o0;
            *reinterpret_cast<ulonglong2*>(hnxt + row * SPC + 8 * tp + 4) = o1;
        }
        asm volatile("bar.sync %0, 256;" :: "r"(rh + 1) : "memory");
    }

    __syncthreads();   // join both halves before the head

    // ================= output head: softplus(h_T @ fc_W^T + fc_b) =================
    const float* hf = hsp0;   // S_LEN even -> final state in buffer 0 (splatted)
    if (tid < ROWS * D_OUT) {
        const int r = tid / D_OUT;
        const int o = tid % D_OUT;
        const int grow = cb + r;
        if (grow < B_TOT) {
            float z = fc_b[o];
            const float* wrow = fc_W + o * HID;
            const float* hrow = hf + r * SPC;
            #pragma unroll
            for (int j = 0; j < HID; j++)
                z = fmaf(wrow[j], hrow[2 * j], z);
            out[grow * D_OUT + o] = softplus_acc(z);
        }
    }
}

extern "C" void kernel_launch(void* const* d_in, const int* in_sizes, int n_in,
                              void* d_out, int out_size) {
    const float* x       = (const float*)d_in[0];
    const float* W_xh    = (const float*)d_in[1];
    const float* W_hh    = (const float*)d_in[2];
    const float* b_hh    = (const float*)d_in[3];
    const float* log_tau = (const float*)d_in[4];
    const float* fc_W    = (const float*)d_in[5];
    const float* fc_b    = (const float*)d_in[6];
    float* out = (float*)d_out;

    const size_t shmem = (size_t)(XSZ + 2 * HSPSZ + PARTSZ) * sizeof(float); // 129024 B
    cudaFuncSetAttribute(cfc_kernel, cudaFuncAttributeMaxDynamicSharedMemorySize, (int)shmem);

    cfc_kernel<<<NCTA, NTHR, shmem>>>(x, W_xh, W_hh, b_hh, log_tau, fc_W, fc_b, out);
}